// round 9
// baseline (speedup 1.0000x reference)
#include <cuda_runtime.h>
#include <math.h>

#define N_PTS 16384
#define MAXNB 64
#define NCLOUD 8
#define GDIM 16
#define NCELLS (NCLOUD*GDIM*GDIM*GDIM)   // 32768
#define CAP 32
#define FULL 0xffffffffu

// ---- scratch (device globals; no allocation allowed) ----
__device__ int    d_count[NCELLS];
__device__ int    d_cell[NCELLS*CAP];
__device__ float4 d_pos4[N_PTS];                 // x,y,z,sq
__device__ int    d_nbr[N_PTS*MAXNB];
__device__ int    d_cnt[N_PTS];
__device__ float4 d_ua[N_PTS*2],  d_va[N_PTS*2];   // 8 ch as 2x float4
__device__ float4 d_ub[N_PTS*4],  d_vb[N_PTS*4];   // 16 ch as 4x float4
__device__ float  d_uc[N_PTS*32], d_vc[N_PTS*32];

// thread-per-point: pack pos4, insert into grid, layer-a u/v prep, aux copies
__global__ void fill_grid(const float* __restrict__ pos, const int* __restrict__ batch,
                          const float* __restrict__ W1a, const float* __restrict__ b1a,
                          float* __restrict__ out, int aux) {
    int i = blockIdx.x * blockDim.x + threadIdx.x;
    if (i >= N_PTS) return;
    float px = pos[3*i+0], py = pos[3*i+1], pz = pos[3*i+2];
    float sq = (px*px + py*py) + pz*pz;          // match jnp.sum(pos*pos) order
    d_pos4[i] = make_float4(px, py, pz, sq);
    int c  = batch[i];
    int cx = min(GDIM-1, (int)(px * GDIM));
    int cy = min(GDIM-1, (int)(py * GDIM));
    int cz = min(GDIM-1, (int)(pz * GDIM));
    int cell = ((c * GDIM + cz) * GDIM + cy) * GDIM + cx;
    int slot = atomicAdd(&d_count[cell], 1);
    if (slot < CAP) d_cell[cell*CAP + slot] = i;
    // layer-a prep: u_a = b1 + pos@W1x + pos@W1p ; v_a = pos@W1p (input x == pos)
    float ua[8], va[8];
    #pragma unroll
    for (int m = 0; m < 8; m++) {
        float tf = px*W1a[0*8+m] + py*W1a[1*8+m] + pz*W1a[2*8+m];
        float tp = px*W1a[3*8+m] + py*W1a[4*8+m] + pz*W1a[5*8+m];
        ua[m] = b1a[m] + tf + tp;
        va[m] = tp;
    }
    d_ua[i*2+0] = make_float4(ua[0],ua[1],ua[2],ua[3]);
    d_ua[i*2+1] = make_float4(ua[4],ua[5],ua[6],ua[7]);
    d_va[i*2+0] = make_float4(va[0],va[1],va[2],va[3]);
    d_va[i*2+1] = make_float4(va[4],va[5],va[6],va[7]);
    if (aux) {
        out[3*i+0] = px; out[3*i+1] = py; out[3*i+2] = pz;
        out[N_PTS*3 + N_PTS*32 + i] = (float)c;
    }
}

// thread-per-point: stencil radius scan + inline layer-a conv + layer-b u/v prep
__global__ void __launch_bounds__(64)
build_conv_a(const int* __restrict__ batch,
             const float* __restrict__ W2, const float* __restrict__ b2,
             const float* __restrict__ W1n, const float* __restrict__ b1n) {
    int i = blockIdx.x * blockDim.x + threadIdx.x;
    if (i >= N_PTS) return;
    float4 p = d_pos4[i];
    const float r2 = (1.0f/16.0f) * (1.0f/16.0f);
    int c  = batch[i];
    int cx = min(GDIM-1, (int)(p.x * GDIM));
    int cy = min(GDIM-1, (int)(p.y * GDIM));
    int cz = min(GDIM-1, (int)(p.z * GDIM));

    float4 v0 = d_va[i*2+0], v1 = d_va[i*2+1];
    float best[8];
    #pragma unroll
    for (int m = 0; m < 8; m++) best[m] = -INFINITY;

    int cnt = 0;
    for (int dz = max(cz-1,0); dz <= min(cz+1,GDIM-1); dz++)
    for (int dy = max(cy-1,0); dy <= min(cy+1,GDIM-1); dy++)
    for (int dx = max(cx-1,0); dx <= min(cx+1,GDIM-1); dx++) {
        int cell = ((c * GDIM + dz) * GDIM + dy) * GDIM + dx;
        int m = min(d_count[cell], CAP);
        for (int t = 0; t < m; t++) {
            int j = d_cell[cell*CAP + t];
            float4 q = d_pos4[j];
            float dot = (p.x*q.x + p.y*q.y) + p.z*q.z;
            float d2  = fmaxf(p.w + q.w - 2.0f*dot, 0.0f);   // exact reference formula
            if (d2 <= r2 && cnt < MAXNB) {
                d_nbr[i*MAXNB + cnt++] = j;
                float4 u0 = d_ua[j*2+0], u1 = d_ua[j*2+1];
                best[0] = fmaxf(best[0], fmaxf(u0.x - v0.x, 0.0f));
                best[1] = fmaxf(best[1], fmaxf(u0.y - v0.y, 0.0f));
                best[2] = fmaxf(best[2], fmaxf(u0.z - v0.z, 0.0f));
                best[3] = fmaxf(best[3], fmaxf(u0.w - v0.w, 0.0f));
                best[4] = fmaxf(best[4], fmaxf(u1.x - v1.x, 0.0f));
                best[5] = fmaxf(best[5], fmaxf(u1.y - v1.y, 0.0f));
                best[6] = fmaxf(best[6], fmaxf(u1.z - v1.z, 0.0f));
                best[7] = fmaxf(best[7], fmaxf(u1.w - v1.w, 0.0f));
            }
        }
    }
    d_cnt[i] = cnt;
    #pragma unroll
    for (int m = 0; m < 8; m++) if (!isfinite(best[m])) best[m] = 0.0f;

    // second linear 8x8 + celu
    float oa[8];
    #pragma unroll
    for (int o = 0; o < 8; o++) {
        float a0 = b2[o], a1 = 0.0f;
        #pragma unroll
        for (int m = 0; m < 4; m++) a0 += best[m]   * W2[m*8+o];
        #pragma unroll
        for (int m = 4; m < 8; m++) a1 += best[m]   * W2[m*8+o];
        float a = a0 + a1;
        oa[o] = (a > 0.0f) ? a : expm1f(a);
    }

    // layer-b prep: 16 channels
    float ub[16], vb[16];
    #pragma unroll
    for (int m = 0; m < 16; m++) {
        float tp = p.x*W1n[8*16+m] + p.y*W1n[9*16+m] + p.z*W1n[10*16+m];
        float u0 = b1n[m] + tp, u1 = 0.0f;
        #pragma unroll
        for (int f = 0; f < 4; f++) u0 += oa[f] * W1n[f*16+m];
        #pragma unroll
        for (int f = 4; f < 8; f++) u1 += oa[f] * W1n[f*16+m];
        ub[m] = u0 + u1;
        vb[m] = tp;
    }
    #pragma unroll
    for (int q = 0; q < 4; q++) {
        d_ub[i*4+q] = make_float4(ub[4*q],ub[4*q+1],ub[4*q+2],ub[4*q+3]);
        d_vb[i*4+q] = make_float4(vb[4*q],vb[4*q+1],vb[4*q+2],vb[4*q+3]);
    }
}

// layer b conv: 2 points/warp, 16-lane group = 16 channels; + layer-c u/v prep
__global__ void conv_b(const float* __restrict__ W2, const float* __restrict__ b2,
                       const float* __restrict__ W1n, const float* __restrict__ b1n) {
    int lane = threadIdx.x & 31;
    int warp = (blockIdx.x * blockDim.x + threadIdx.x) >> 5;   // 0..8191 exactly
    const int g = lane >> 4, m = lane & 15;
    const int i = warp * 2 + g;
    float v = ((const float*)d_vb)[i*16+m];
    int cnt = d_cnt[i];
    float best = -INFINITY;
    for (int k = 0; k < cnt; k++) {
        int j = d_nbr[i*MAXNB + k];
        best = fmaxf(best, fmaxf(((const float*)d_ub)[j*16+m] - v, 0.0f));
    }
    if (!isfinite(best)) best = 0.0f;
    float a0 = b2[m], a1 = 0.0f;
    #pragma unroll
    for (int mm = 0; mm < 8; mm++)
        a0 += __shfl_sync(FULL, best, mm, 16) * W2[mm*16+m];
    #pragma unroll
    for (int mm = 8; mm < 16; mm++)
        a1 += __shfl_sync(FULL, best, mm, 16) * W2[mm*16+m];
    float acc = a0 + a1;
    acc = (acc > 0.0f) ? acc : expm1f(acc);      // lane m of group holds out[m]
    // layer-c prep: channels m and m+16
    float4 p = d_pos4[i];
    float tp0 = p.x*W1n[16*32+m]    + p.y*W1n[17*32+m]    + p.z*W1n[18*32+m];
    float tp1 = p.x*W1n[16*32+m+16] + p.y*W1n[17*32+m+16] + p.z*W1n[18*32+m+16];
    float u0 = b1n[m]    + tp0;
    float u1 = b1n[m+16] + tp1;
    #pragma unroll
    for (int f = 0; f < 16; f++) {
        float xf = __shfl_sync(FULL, acc, f, 16);
        u0 += xf * W1n[f*32+m];
        u1 += xf * W1n[f*32+m+16];
    }
    d_uc[i*32+m]    = u0;  d_vc[i*32+m]    = tp0;
    d_uc[i*32+m+16] = u1;  d_vc[i*32+m+16] = tp1;
}

// layer c conv (CMID=32, warp-per-point) -> final output
__global__ void conv_c(const float* __restrict__ W2, const float* __restrict__ b2,
                       float* __restrict__ outp) {
    int warp = (blockIdx.x * blockDim.x + threadIdx.x) >> 5;
    int lane = threadIdx.x & 31;
    const int i = warp;                          // 0..16383 exactly
    float v = d_vc[i*32+lane];
    int cnt = d_cnt[i];
    float best = -INFINITY;
    for (int k = 0; k < cnt; k++) {
        int j = d_nbr[i*MAXNB + k];
        best = fmaxf(best, fmaxf(d_uc[j*32+lane] - v, 0.0f));
    }
    if (!isfinite(best)) best = 0.0f;
    float a0 = b2[lane], a1 = 0.0f;
    #pragma unroll
    for (int mm = 0; mm < 16; mm++)
        a0 += __shfl_sync(FULL, best, mm) * W2[mm*32+lane];
    #pragma unroll
    for (int mm = 16; mm < 32; mm++)
        a1 += __shfl_sync(FULL, best, mm) * W2[mm*32+lane];
    float acc = a0 + a1;
    acc = (acc > 0.0f) ? acc : expm1f(acc);
    outp[i*32+lane] = acc;
}

extern "C" void kernel_launch(void* const* d_in, const int* in_sizes, int n_in,
                              void* d_out, int out_size) {
    const float* pos   = (const float*)d_in[0];
    const int*   batch = (const int*)d_in[2];
    const float* W1a = (const float*)d_in[3];
    const float* b1a = (const float*)d_in[4];
    const float* W2a = (const float*)d_in[5];
    const float* b2a = (const float*)d_in[6];
    const float* W1b = (const float*)d_in[7];
    const float* b1b = (const float*)d_in[8];
    const float* W2b = (const float*)d_in[9];
    const float* b2b = (const float*)d_in[10];
    const float* W1c = (const float*)d_in[11];
    const float* b1c = (const float*)d_in[12];
    const float* W2c = (const float*)d_in[13];
    const float* b2c = (const float*)d_in[14];

    float* out = (float*)d_out;
    const int full_size = N_PTS*3 + N_PTS*32 + N_PTS;   // pos + feat + batch
    const int aux = (out_size >= full_size) ? 1 : 0;
    float* feat_out = out + (aux ? N_PTS*3 : 0);

    void* count_ptr = nullptr;
    cudaGetSymbolAddress(&count_ptr, d_count);
    cudaMemsetAsync(count_ptr, 0, NCELLS * sizeof(int));

    fill_grid   <<<N_PTS/128, 128>>>(pos, batch, W1a, b1a, out, aux);
    build_conv_a<<<N_PTS/64,   64>>>(batch, W2a, b2a, W1b, b1b);

    conv_b<<<(N_PTS/2)*32/256, 256>>>(W2b, b2b, W1c, b1c);   // 1024 blocks
    conv_c<<< N_PTS   *32/256, 256>>>(W2c, b2c, feat_out);   // 2048 blocks
}